// round 1
// baseline (speedup 1.0000x reference)
#include <cuda_runtime.h>

// Problem constants
#define B_SZ 2
#define T_SZ 2048
#define C_SZ 1024
#define NH   16
#define HD   64
#define M_ROWS (B_SZ * T_SZ)     // 4096
#define N_QKV  (3 * C_SZ)        // 3072

// Scratch (no allocations allowed -> __device__ globals)
__device__ float g_q[(size_t)B_SZ * NH * T_SZ * HD];   // [B,H,T,hd]
__device__ float g_k[(size_t)B_SZ * NH * T_SZ * HD];
__device__ float g_v[(size_t)B_SZ * NH * T_SZ * HD];
__device__ float g_att[(size_t)M_ROWS * C_SZ];         // [B,T,C]

// ---------------------------------------------------------------------------
// SGEMM: C = A @ B + bias, 128x128 block tile, BK=8, 8x8 per thread, 256 thr
// MODE 0: A = x, epilogue scatters qkv into g_q/g_k/g_v ([B,H,T,hd])
// MODE 1: A = g_att, epilogue writes Cout row-major
// ---------------------------------------------------------------------------
#define BM 128
#define BN 128
#define BK 8
#define TM 8
#define TN 8

template <int MODE>
__global__ __launch_bounds__(256, 2)
void sgemm_bias(const float* __restrict__ A,
                const float* __restrict__ Bmat,
                const float* __restrict__ bias,
                float* __restrict__ Cout,
                int M, int N, int K)
{
    __shared__ float As[BK][BM];
    __shared__ float Bs[BK][BN];

    const int tid = threadIdx.x;
    const int bx = blockIdx.x, by = blockIdx.y;

    const float* Ap = (MODE == 1) ? g_att : A;

    // A tile loader: 128 rows x 8 cols, one float4 per thread
    const int rowA = tid >> 1;
    const int colA = (tid & 1) * 4;
    // B tile loader: 8 rows x 128 cols, one float4 per thread
    const int rowB = tid >> 5;
    const int colB = (tid & 31) * 4;

    const float* Abase = Ap + (size_t)(by * BM) * K;
    const float* Bbase = Bmat + (size_t)(bx * BN);

    const int tx = tid & 15;
    const int ty = tid >> 4;

    float acc[TM][TN];
    #pragma unroll
    for (int i = 0; i < TM; i++)
        #pragma unroll
        for (int j = 0; j < TN; j++)
            acc[i][j] = 0.0f;

    for (int k0 = 0; k0 < K; k0 += BK) {
        float4 a4 = *reinterpret_cast<const float4*>(Abase + (size_t)rowA * K + k0 + colA);
        As[colA + 0][rowA] = a4.x;
        As[colA + 1][rowA] = a4.y;
        As[colA + 2][rowA] = a4.z;
        As[colA + 3][rowA] = a4.w;
        *reinterpret_cast<float4*>(&Bs[rowB][colB]) =
            *reinterpret_cast<const float4*>(Bbase + (size_t)(k0 + rowB) * N + colB);
        __syncthreads();

        #pragma unroll
        for (int kk = 0; kk < BK; kk++) {
            float ra[TM], rb[TN];
            *reinterpret_cast<float4*>(&ra[0]) = *reinterpret_cast<const float4*>(&As[kk][ty * TM]);
            *reinterpret_cast<float4*>(&ra[4]) = *reinterpret_cast<const float4*>(&As[kk][ty * TM + 4]);
            *reinterpret_cast<float4*>(&rb[0]) = *reinterpret_cast<const float4*>(&Bs[kk][tx * TN]);
            *reinterpret_cast<float4*>(&rb[4]) = *reinterpret_cast<const float4*>(&Bs[kk][tx * TN + 4]);
            #pragma unroll
            for (int i = 0; i < TM; i++)
                #pragma unroll
                for (int j = 0; j < TN; j++)
                    acc[i][j] = fmaf(ra[i], rb[j], acc[i][j]);
        }
        __syncthreads();
    }

    const int mbase = by * BM + ty * TM;
    const int nbase = bx * BN + tx * TN;

    if (MODE == 0) {
        // n -> head h = n/192, inner = n%192 ; inner<64 -> q, <128 -> k, else v
        #pragma unroll
        for (int j = 0; j < TN; j++) {
            const int n = nbase + j;
            const int h = n / 192;
            const int inner = n - h * 192;
            const int which = inner >> 6;
            const int d = inner & 63;
            const float bv = bias[n];
            float* dst = (which == 0) ? g_q : (which == 1) ? g_k : g_v;
            #pragma unroll
            for (int i = 0; i < TM; i++) {
                const int mm = mbase + i;
                const int b = mm >> 11;           // /2048
                const int t = mm & (T_SZ - 1);
                dst[(((size_t)(b * NH + h) * T_SZ + t) * HD) + d] = acc[i][j] + bv;
            }
        }
    } else {
        #pragma unroll
        for (int i = 0; i < TM; i++) {
            const int mm = mbase + i;
            #pragma unroll
            for (int j = 0; j < TN; j++) {
                const int n = nbase + j;
                Cout[(size_t)mm * N + n] = acc[i][j] + bias[n];
            }
        }
    }
}

// ---------------------------------------------------------------------------
// Causal flash attention. grid = (T/64, B*NH), 256 threads.
// Br=Bc=64, hd=64. Dynamic smem: Qt[64][64] + Kt[64][64] + Vs[64][64] + Ss[64][65]
// Phase A: S = Q K^T / 8 (4x4 per thread, 16x16 thread grid), causal-masked.
// Phase B: per-row online softmax (4 consecutive lanes per row), O accumulated
// in registers (1 row x 16 dims per thread).
// ---------------------------------------------------------------------------
#define FA_SMEM_FLOATS (3 * 64 * 64 + 64 * 65)
#define FA_SMEM_BYTES  (FA_SMEM_FLOATS * 4)

__global__ __launch_bounds__(256, 3)
void flash_attn()
{
    extern __shared__ float sm[];
    float* Qt = sm;                 // [d][i]  d-major
    float* Kt = sm + 64 * 64;       // [d][j]
    float* Vs = sm + 2 * 64 * 64;   // [j][d]
    float* Ss = sm + 3 * 64 * 64;   // [i][j], leading dim 65 (bank-conflict pad)

    const int tid = threadIdx.x;
    const int bh = blockIdx.y;                  // b*NH + h
    const int qbase = blockIdx.x * 64;
    const size_t base = (size_t)bh * T_SZ * HD;
    const float* qp = g_q + base;
    const float* kp = g_k + base;
    const float* vp = g_v + base;

    const int li = tid >> 2;        // row 0..63 (loader row & phase-B row)
    const int c0 = (tid & 3) * 16;  // 16-wide chunk (cols of S / dims of V,O)

    // Load Q tile transposed
    #pragma unroll
    for (int u = 0; u < 16; u += 4) {
        float4 v4 = *reinterpret_cast<const float4*>(qp + (size_t)(qbase + li) * HD + c0 + u);
        Qt[(c0 + u + 0) * 64 + li] = v4.x;
        Qt[(c0 + u + 1) * 64 + li] = v4.y;
        Qt[(c0 + u + 2) * 64 + li] = v4.z;
        Qt[(c0 + u + 3) * 64 + li] = v4.w;
    }

    const int tx = tid & 15;        // phase-A col group (4 cols)
    const int ty = tid >> 4;        // phase-A row group (4 rows)
    const int qg0 = qbase + ty * 4;

    float m = -1e30f, l = 0.0f;
    float o[16];
    #pragma unroll
    for (int i = 0; i < 16; i++) o[i] = 0.0f;
    const float inv_scale = 0.125f;  // 1/sqrt(64)

    const int ntiles = blockIdx.x + 1;   // causal: tiles 0..qtile
    for (int kt = 0; kt < ntiles; kt++) {
        const int kbase = kt * 64;
        __syncthreads();   // prior phase-B reads of Vs/Ss complete

        // Load K (transposed) and V (natural)
        #pragma unroll
        for (int u = 0; u < 16; u += 4) {
            float4 kk = *reinterpret_cast<const float4*>(kp + (size_t)(kbase + li) * HD + c0 + u);
            Kt[(c0 + u + 0) * 64 + li] = kk.x;
            Kt[(c0 + u + 1) * 64 + li] = kk.y;
            Kt[(c0 + u + 2) * 64 + li] = kk.z;
            Kt[(c0 + u + 3) * 64 + li] = kk.w;
            *reinterpret_cast<float4*>(&Vs[li * 64 + c0 + u]) =
                *reinterpret_cast<const float4*>(vp + (size_t)(kbase + li) * HD + c0 + u);
        }
        __syncthreads();

        // Phase A: S tile
        {
            float acc[4][4];
            #pragma unroll
            for (int i = 0; i < 4; i++)
                #pragma unroll
                for (int j = 0; j < 4; j++) acc[i][j] = 0.0f;

            #pragma unroll 8
            for (int d = 0; d < HD; d++) {
                float ra[4], rb[4];
                *reinterpret_cast<float4*>(ra) = *reinterpret_cast<const float4*>(&Qt[d * 64 + ty * 4]);
                *reinterpret_cast<float4*>(rb) = *reinterpret_cast<const float4*>(&Kt[d * 64 + tx * 4]);
                #pragma unroll
                for (int i = 0; i < 4; i++)
                    #pragma unroll
                    for (int j = 0; j < 4; j++)
                        acc[i][j] = fmaf(ra[i], rb[j], acc[i][j]);
            }
            #pragma unroll
            for (int i = 0; i < 4; i++) {
                const int gi = qg0 + i;
                #pragma unroll
                for (int j = 0; j < 4; j++) {
                    const int gj = kbase + tx * 4 + j;
                    Ss[(ty * 4 + i) * 65 + tx * 4 + j] =
                        (gj <= gi) ? acc[i][j] * inv_scale : -1e30f;
                }
            }
        }
        __syncthreads();

        // Phase B: online softmax + O update (row li, dims c0..c0+15)
        float lmax = -1e30f;
        #pragma unroll
        for (int j = 0; j < 16; j++)
            lmax = fmaxf(lmax, Ss[li * 65 + c0 + j]);
        lmax = fmaxf(lmax, __shfl_xor_sync(0xffffffffu, lmax, 1));
        lmax = fmaxf(lmax, __shfl_xor_sync(0xffffffffu, lmax, 2));

        const float mnew = fmaxf(m, lmax);
        const float alpha = __expf(m - mnew);
        float lsum = 0.0f;
        #pragma unroll
        for (int j = 0; j < 16; j++) {
            const float p = __expf(Ss[li * 65 + c0 + j] - mnew);
            Ss[li * 65 + c0 + j] = p;
            lsum += p;
        }
        lsum += __shfl_xor_sync(0xffffffffu, lsum, 1);
        lsum += __shfl_xor_sync(0xffffffffu, lsum, 2);
        l = l * alpha + lsum;
        m = mnew;

        #pragma unroll
        for (int i = 0; i < 16; i++) o[i] *= alpha;
        __syncwarp();   // p-writes to Ss row (split across the 4 group lanes) visible

        #pragma unroll 8
        for (int j = 0; j < 64; j++) {
            const float p = Ss[li * 65 + j];
            float rv[4];
            *reinterpret_cast<float4*>(rv) = *reinterpret_cast<const float4*>(&Vs[j * 64 + c0]);
            o[0] = fmaf(p, rv[0], o[0]);  o[1] = fmaf(p, rv[1], o[1]);
            o[2] = fmaf(p, rv[2], o[2]);  o[3] = fmaf(p, rv[3], o[3]);
            *reinterpret_cast<float4*>(rv) = *reinterpret_cast<const float4*>(&Vs[j * 64 + c0 + 4]);
            o[4] = fmaf(p, rv[0], o[4]);  o[5] = fmaf(p, rv[1], o[5]);
            o[6] = fmaf(p, rv[2], o[6]);  o[7] = fmaf(p, rv[3], o[7]);
            *reinterpret_cast<float4*>(rv) = *reinterpret_cast<const float4*>(&Vs[j * 64 + c0 + 8]);
            o[8] = fmaf(p, rv[0], o[8]);  o[9] = fmaf(p, rv[1], o[9]);
            o[10] = fmaf(p, rv[2], o[10]); o[11] = fmaf(p, rv[3], o[11]);
            *reinterpret_cast<float4*>(rv) = *reinterpret_cast<const float4*>(&Vs[j * 64 + c0 + 12]);
            o[12] = fmaf(p, rv[0], o[12]); o[13] = fmaf(p, rv[1], o[13]);
            o[14] = fmaf(p, rv[2], o[14]); o[15] = fmaf(p, rv[3], o[15]);
        }
    }

    // Normalize and store into [B,T,C] layout
    const float inv_l = 1.0f / l;
    const int b = bh >> 4, h = bh & (NH - 1);
    float* outp = g_att + (size_t)(b * T_SZ + qbase + li) * C_SZ + h * HD + c0;
    #pragma unroll
    for (int u = 0; u < 16; u += 4) {
        float4 w;
        w.x = o[u + 0] * inv_l;
        w.y = o[u + 1] * inv_l;
        w.z = o[u + 2] * inv_l;
        w.w = o[u + 3] * inv_l;
        *reinterpret_cast<float4*>(outp + u) = w;
    }
}

// ---------------------------------------------------------------------------
extern "C" void kernel_launch(void* const* d_in, const int* in_sizes, int n_in,
                              void* d_out, int out_size)
{
    const float* x     = (const float*)d_in[0];
    const float* Wqkv  = (const float*)d_in[1];
    const float* bqkv  = (const float*)d_in[2];
    const float* Wproj = (const float*)d_in[3];
    const float* bproj = (const float*)d_in[4];
    float* out = (float*)d_out;
    (void)in_sizes; (void)n_in; (void)out_size;

    cudaFuncSetAttribute(flash_attn, cudaFuncAttributeMaxDynamicSharedMemorySize,
                         FA_SMEM_BYTES);

    // 1) QKV projection + scatter to [B,H,T,hd]
    sgemm_bias<0><<<dim3(N_QKV / BN, M_ROWS / BM), 256>>>(
        x, Wqkv, bqkv, nullptr, M_ROWS, N_QKV, C_SZ);

    // 2) Causal flash attention -> g_att [B,T,C]
    flash_attn<<<dim3(T_SZ / 64, B_SZ * NH), 256, FA_SMEM_BYTES>>>();

    // 3) Output projection
    sgemm_bias<1><<<dim3(C_SZ / BN, M_ROWS / BM), 256>>>(
        nullptr, Wproj, bproj, out, M_ROWS, C_SZ, C_SZ);
}